// round 2
// baseline (speedup 1.0000x reference)
#include <cuda_runtime.h>

// Problem constants
#define M_TOT 4096   // B*N*H*W = 32*8*16
#define C_TOT 256
#define TM 64        // rows per CTA tile
#define TN 128       // cols per CTA tile
#define NRB (M_TOT / TM)   // 64 row blocks
#define NCT (M_TOT / TN)   // 32 col tiles

// Scratch (allocation-free: __device__ globals)
__device__ __align__(16) float g_pT[C_TOT * M_TOT];   // pred, k-major [C][M]
__device__ __align__(16) float g_gT[C_TOT * M_TOT];   // gt,   k-major [C][M]
__device__ float g_diag[M_TOT];
__device__ float g_pmax[M_TOT * NCT];
__device__ float g_psum[M_TOT * NCT];
__device__ int   g_pami[M_TOT * NCT];

// ---------------------------------------------------------------------------
// Kernel 0: pack (B,N,C,H,W) -> k-major [C][M] for both pred and gt.
// Input element for (m, c):  page = m>>4 (b*N+n), hw = m&15
//   addr = page*C*16 + c*16 + hw
// Output float index o = c*M_TOT + m  (m fastest -> coalesced writes).
// Reads: per float4 at m%4==0, hw%4==0 -> contiguous 16B -> coalesced.
// ---------------------------------------------------------------------------
__global__ void pack_kernel(const float4* __restrict__ pred,
                            const float4* __restrict__ gt) {
    const int NF4 = C_TOT * M_TOT / 4;  // 262144 per tensor
    int q = blockIdx.x * blockDim.x + threadIdx.x;
    if (q >= 2 * NF4) return;

    float4* dst;
    const float4* src;
    int qq = q;
    if (qq < NF4) { dst = (float4*)g_pT; src = pred; }
    else          { dst = (float4*)g_gT; src = gt; qq -= NF4; }

    int c  = qq >> 10;          // (qq*4) / 4096
    int m  = (qq & 1023) << 2;  // m, multiple of 4
    int page = m >> 4;
    int hw   = m & 15;          // multiple of 4
    int in_f = page * (C_TOT * 16) + c * 16 + hw;
    dst[qq] = src[in_f >> 2];
}

// ---------------------------------------------------------------------------
// Kernel 1: fused GEMM + online row-softmax stats.
// One CTA = one 64x128 tile of lossmat, K=256 fully in smem.
// smem: p_s [256][64] (64KB, k-major) + g_s [256][128] (128KB, k-major).
// 256 threads; warp ty=tid>>5 owns rows ty*8..+7 (A loads are warp-broadcast),
// lane tx owns cols tx*4..+3 (B loads conflict-free LDS.128).
// Per thread: 8x4 accumulators -> 32 FMA per 48B LDS -> FMA-bound.
// After K loop: per-row (max, sumexp, argmax) via warp butterfly; lane 0
// writes partials at [row][coltile]; diag captured where gcol==grow.
// ---------------------------------------------------------------------------
__global__ void __launch_bounds__(256, 1) gemm_softmax_kernel() {
    extern __shared__ float sm[];
    float* p_s = sm;                 // [256][64]
    float* g_s = sm + C_TOT * TM;    // [256][128]

    const int rb  = blockIdx.x >> 5;   // row block 0..63
    const int ct  = blockIdx.x & 31;   // col tile  0..31
    const int tid = threadIdx.x;

    // --- load tiles (k-major, coalesced) ---
    {
        float4* ps4 = (float4*)p_s;
        const float4* srcp = (const float4*)g_pT;
        #pragma unroll
        for (int q = tid; q < C_TOT * TM / 4; q += 256) {
            int k = q >> 4, off = q & 15;
            ps4[q] = srcp[k * (M_TOT / 4) + rb * (TM / 4) + off];
        }
        float4* gs4 = (float4*)g_s;
        const float4* srcg = (const float4*)g_gT;
        #pragma unroll
        for (int q = tid; q < C_TOT * TN / 4; q += 256) {
            int k = q >> 5, off = q & 31;
            gs4[q] = srcg[k * (M_TOT / 4) + ct * (TN / 4) + off];
        }
    }
    __syncthreads();

    const int ty = tid >> 5;   // 0..7  (warp id -> row group)
    const int tx = tid & 31;   // 0..31 (lane -> col group)

    float acc[8][4];
    #pragma unroll
    for (int i = 0; i < 8; i++)
        #pragma unroll
        for (int j = 0; j < 4; j++) acc[i][j] = 0.f;

    #pragma unroll 4
    for (int k = 0; k < C_TOT; k++) {
        float4 a0 = *(const float4*)&p_s[k * TM + ty * 8];
        float4 a1 = *(const float4*)&p_s[k * TM + ty * 8 + 4];
        float4 b  = *(const float4*)&g_s[k * TN + tx * 4];
        float av[8] = {a0.x, a0.y, a0.z, a0.w, a1.x, a1.y, a1.z, a1.w};
        float bv[4] = {b.x, b.y, b.z, b.w};
        #pragma unroll
        for (int i = 0; i < 8; i++)
            #pragma unroll
            for (int j = 0; j < 4; j++)
                acc[i][j] = fmaf(av[i], bv[j], acc[i][j]);
    }

    // --- per-row online-softmax stats ---
    const int col0 = ct * TN + tx * 4;
    #pragma unroll
    for (int i = 0; i < 8; i++) {
        const int grow = rb * TM + ty * 8 + i;

        // thread-local max / argmax (first-index tie-break) over 4 cols
        float m = acc[i][0];
        int   ai = col0;
        #pragma unroll
        for (int j = 1; j < 4; j++) {
            if (acc[i][j] > m) { m = acc[i][j]; ai = col0 + j; }
        }
        float s = 0.f;
        #pragma unroll
        for (int j = 0; j < 4; j++) s += __expf(acc[i][j] - m);

        // diag capture (at most one thread matches per row)
        #pragma unroll
        for (int j = 0; j < 4; j++)
            if (col0 + j == grow) g_diag[grow] = acc[i][j];

        // warp butterfly merge across the 32 lanes covering this row's 128 cols
        #pragma unroll
        for (int off = 16; off > 0; off >>= 1) {
            float m2 = __shfl_xor_sync(0xffffffffu, m, off);
            float s2 = __shfl_xor_sync(0xffffffffu, s, off);
            int   a2 = __shfl_xor_sync(0xffffffffu, ai, off);
            // argmax value IS the row max; tie -> smaller index (jnp.argmax)
            if (m2 > m || (m2 == m && a2 < ai)) ai = a2;
            float Mx = fmaxf(m, m2);
            s = s * __expf(m - Mx) + s2 * __expf(m2 - Mx);
            m = Mx;
        }
        if (tx == 0) {
            int pi = grow * NCT + ct;
            g_pmax[pi] = m;
            g_psum[pi] = s;
            g_pami[pi] = ai;
        }
    }
}

// ---------------------------------------------------------------------------
// Kernel 2: finalize. Reduce 32 partials per row -> lse, argmax; then
// block-reduce loss and accuracy. Single block, 256 threads.
// ---------------------------------------------------------------------------
__global__ void finalize_kernel(float* __restrict__ out) {
    __shared__ float s_loss[256];
    __shared__ int   s_corr[256];
    const int tid = threadIdx.x;

    float lsum = 0.f;
    int   csum = 0;
    for (int r = tid; r < M_TOT; r += 256) {
        const float* pm = &g_pmax[r * NCT];
        const float* ps = &g_psum[r * NCT];
        const int*   pa = &g_pami[r * NCT];

        float Mx = -3.4e38f;
        #pragma unroll
        for (int t = 0; t < NCT; t++) Mx = fmaxf(Mx, pm[t]);

        float S = 0.f;
        float bv = -3.4e38f;
        int   AI = 0;
        #pragma unroll
        for (int t = 0; t < NCT; t++) {
            float v = pm[t];
            S += ps[t] * __expf(v - Mx);
            if (v > bv) { bv = v; AI = pa[t]; }  // ascending t -> first-index ties
        }
        float lse = Mx + logf(S);
        lsum += lse - g_diag[r];
        csum += (AI == r) ? 1 : 0;
    }

    s_loss[tid] = lsum;
    s_corr[tid] = csum;
    __syncthreads();
    for (int o = 128; o > 0; o >>= 1) {
        if (tid < o) {
            s_loss[tid] += s_loss[tid + o];
            s_corr[tid] += s_corr[tid + o];
        }
        __syncthreads();
    }
    if (tid == 0) {
        out[0] = s_loss[0] / (float)M_TOT;                  // loss
        out[1] = 100.f * (float)s_corr[0] / (float)M_TOT;   // accuracy
    }
}

// ---------------------------------------------------------------------------
extern "C" void kernel_launch(void* const* d_in, const int* in_sizes, int n_in,
                              void* d_out, int out_size) {
    const float4* pred = (const float4*)d_in[0];
    const float4* gt   = (const float4*)d_in[1];

    // 192KB dynamic smem for the GEMM kernel (idempotent, capture-safe)
    cudaFuncSetAttribute(gemm_softmax_kernel,
                         cudaFuncAttributeMaxDynamicSharedMemorySize,
                         C_TOT * (TM + TN) * (int)sizeof(float));

    pack_kernel<<<2048, 256>>>(pred, gt);
    gemm_softmax_kernel<<<NRB * NCT, 256, C_TOT * (TM + TN) * sizeof(float)>>>();
    finalize_kernel<<<1, 256>>>((float*)d_out);
}

// round 5
// speedup vs baseline: 1.7340x; 1.7340x over previous
#include <cuda_runtime.h>
#include <cuda_bf16.h>
#include <cstdint>
#include <cfloat>

// ---------------- problem constants ----------------
#define M_TOT 4096          // B*N*H*W
#define C_TOT 256           // K
#define NPAGE 256           // B*N pages (each 16 m's x 256 c's)
#define KC 64               // K chunk (64 bf16 = 128B = SW128 row)
#define NCHUNK (C_TOT / KC) // 4
#define NPART 32            // partials per row = 4096/128

// ---------------- scratch ----------------
__device__ __align__(16) __nv_bfloat16 g_phi[M_TOT * C_TOT];
__device__ __align__(16) __nv_bfloat16 g_plo[M_TOT * C_TOT];
__device__ __align__(16) __nv_bfloat16 g_ghi[M_TOT * C_TOT];
__device__ __align__(16) __nv_bfloat16 g_glo[M_TOT * C_TOT];
__device__ float g_diag[M_TOT];
__device__ float g_pmax[M_TOT * NPART];
__device__ float g_psum[M_TOT * NPART];
__device__ int   g_pami[M_TOT * NPART];

// ---------------- helpers ----------------
__device__ __forceinline__ uint32_t smem_u32(const void* p) {
    uint32_t a;
    asm("{ .reg .u64 t; cvta.to.shared.u64 t, %1; cvt.u32.u64 %0, t; }"
        : "=r"(a) : "l"(p));
    return a;
}
#define SWZ128(o) ((o) ^ (((o) >> 3) & 0x70))

__device__ __forceinline__ void ldsm4(uint32_t* r, uint32_t addr) {
    asm volatile("ldmatrix.sync.aligned.m8n8.x4.shared.b16 {%0,%1,%2,%3}, [%4];"
                 : "=r"(r[0]), "=r"(r[1]), "=r"(r[2]), "=r"(r[3]) : "r"(addr));
}
__device__ __forceinline__ void mma_bf16(float* d, const uint32_t* a,
                                         const uint32_t* b) {
    asm volatile(
        "mma.sync.aligned.m16n8k16.row.col.f32.bf16.bf16.f32 "
        "{%0,%1,%2,%3}, {%4,%5,%6,%7}, {%8,%9}, {%0,%1,%2,%3};"
        : "+f"(d[0]), "+f"(d[1]), "+f"(d[2]), "+f"(d[3])
        : "r"(a[0]), "r"(a[1]), "r"(a[2]), "r"(a[3]), "r"(b[0]), "r"(b[1]));
}

// smem layout (byte offsets in dynamic smem)
#define SM_AHI 0
#define SM_ALO 16384
#define SM_BHI 32768
#define SM_BLO 49152
#define SM_SMX 65536              // float [4][128]
#define SM_SSM (65536 + 2048)     // float [4][128]
#define SM_SAR (65536 + 4096)     // int   [4][128]
#define SM_TOTAL (65536 + 6144)

// ---------------------------------------------------------------------------
// Kernel 0: pack (B,N,C,H,W) f32 -> row-major [M][C] bf16 hi/lo.
// 512 blocks: block b -> tensor (b<256 ? pred : gt), page = b & 255.
// Page = (b*N+n): 16 m's x 256 c's; smem transpose, both sides coalesced.
// ---------------------------------------------------------------------------
__global__ void __launch_bounds__(256) pack_kernel(const float* __restrict__ pred,
                                                   const float* __restrict__ gt) {
    __shared__ float s[16 * 258];
    const int tid = threadIdx.x;
    const int page = blockIdx.x & (NPAGE - 1);
    const bool is_p = blockIdx.x < NPAGE;
    const float* src = (is_p ? pred : gt) + (size_t)page * 4096;
    __nv_bfloat16* dhi = is_p ? g_phi : g_ghi;
    __nv_bfloat16* dlo = is_p ? g_plo : g_glo;

    #pragma unroll
    for (int i = tid; i < 4096; i += 256) {
        int c = i >> 4, hw = i & 15;
        s[hw * 258 + c] = src[i];
    }
    __syncthreads();
    #pragma unroll
    for (int o = tid; o < 4096; o += 256) {
        int hw = o >> 8, c = o & 255;
        float x = s[hw * 258 + c];
        __nv_bfloat16 h = __float2bfloat16(x);
        __nv_bfloat16 l = __float2bfloat16(x - __bfloat162float(h));
        size_t oi = (size_t)(page * 16 + hw) * 256 + c;
        dhi[oi] = h;
        dlo[oi] = l;
    }
}

// ---------------------------------------------------------------------------
// Kernel 1: HMMA GEMM (3-term bf16 split) + fused online row-softmax.
// CTA 128x128 tile; 8 warps as 2(row) x 4(col); warp tile 64x32.
// ---------------------------------------------------------------------------
__global__ void __launch_bounds__(256, 2) gemm_softmax_kernel() {
    extern __shared__ __align__(1024) char sm[];
    const uint32_t sb = smem_u32(sm);
    const int tid  = threadIdx.x;
    const int wid  = tid >> 5;
    const int lane = tid & 31;
    const int rb = blockIdx.x >> 5;   // 0..31 row block
    const int cb = blockIdx.x & 31;   // 0..31 col block

    const int wr = wid >> 2;          // 0..1 warp row (64 rows)
    const int wc = wid & 3;           // 0..3 warp col (32 cols)

    // ldmatrix base byte-offsets (within a 128x64 bf16 chunk, 128B rows)
    const uint32_t offA0 =
        (uint32_t)((wr * 64 + (lane & 15)) * 128 + (lane >> 4) * 16);
    const uint32_t offB0 =
        (uint32_t)((wc * 32 + ((lane >> 4) & 1) * 8 + (lane & 7)) * 128 +
                   ((lane >> 3) & 1) * 16);

    float acc[4][4][4];
    #pragma unroll
    for (int a = 0; a < 4; a++)
        #pragma unroll
        for (int b = 0; b < 4; b++)
            #pragma unroll
            for (int c = 0; c < 4; c++) acc[a][b][c] = 0.f;

    const uint4* srcAh = (const uint4*)g_phi;
    const uint4* srcAl = (const uint4*)g_plo;
    const uint4* srcBh = (const uint4*)g_ghi;
    const uint4* srcBl = (const uint4*)g_glo;

    for (int ch = 0; ch < NCHUNK; ch++) {
        // ---- load chunk: A rows = pred[rb*128..], B rows = gt[cb*128..] ----
        #pragma unroll
        for (int t = tid; t < 1024; t += 256) {
            int r = t >> 3, sg = t & 7;
            uint32_t sw = SWZ128((uint32_t)(r * 128 + sg * 16));
            int giA = (rb * 128 + r) * 32 + ch * 8 + sg;
            int giB = (cb * 128 + r) * 32 + ch * 8 + sg;
            *(uint4*)(sm + SM_AHI + sw) = srcAh[giA];
            *(uint4*)(sm + SM_ALO + sw) = srcAl[giA];
            *(uint4*)(sm + SM_BHI + sw) = srcBh[giB];
            *(uint4*)(sm + SM_BLO + sw) = srcBl[giB];
        }
        __syncthreads();

        // ---- compute: 4 k-steps of 16 ----
        #pragma unroll
        for (int ks = 0; ks < 4; ks++) {
            const uint32_t kx = (uint32_t)(ks * 32);
            uint32_t bhi[2][4], blo[2][4];
            #pragma unroll
            for (int np = 0; np < 2; np++) {
                uint32_t ob = offB0 + np * 2048 + kx;
                ldsm4(bhi[np], sb + SM_BHI + SWZ128(ob));
                ldsm4(blo[np], sb + SM_BLO + SWZ128(ob));
            }
            #pragma unroll
            for (int mt = 0; mt < 4; mt++) {
                uint32_t oa = offA0 + mt * 2048 + kx;
                uint32_t ahi[4], alo[4];
                ldsm4(ahi, sb + SM_AHI + SWZ128(oa));
                ldsm4(alo, sb + SM_ALO + SWZ128(oa));
                #pragma unroll
                for (int nt = 0; nt < 4; nt++) {
                    const uint32_t* bh = &bhi[nt >> 1][(nt & 1) * 2];
                    const uint32_t* bl = &blo[nt >> 1][(nt & 1) * 2];
                    mma_bf16(acc[mt][nt], ahi, bh);   // hi*hi
                    mma_bf16(acc[mt][nt], ahi, bl);   // hi*lo
                    mma_bf16(acc[mt][nt], alo, bh);   // lo*hi
                }
            }
        }
        __syncthreads();
    }

    // ---- epilogue: per-thread row stats over its 8 cols ----
    const int g  = lane >> 2;
    const int qc = lane & 3;
    float* smax = (float*)(sm + SM_SMX);
    float* ssum = (float*)(sm + SM_SSM);
    int*   sarg = (int*)(sm + SM_SAR);

    #pragma unroll
    for (int mt = 0; mt < 4; mt++) {
        #pragma unroll
        for (int rp = 0; rp < 2; rp++) {
            const int lrow = wr * 64 + mt * 16 + rp * 8 + g;
            const int grow = rb * 128 + lrow;

            float m = -FLT_MAX;
            int ai = 0;
            #pragma unroll
            for (int nt = 0; nt < 4; nt++) {
                #pragma unroll
                for (int cp = 0; cp < 2; cp++) {
                    float x = acc[mt][nt][rp * 2 + cp];
                    int col = cb * 128 + wc * 32 + nt * 8 + qc * 2 + cp;
                    if (col == grow) g_diag[grow] = x;
                    if (x > m) { m = x; ai = col; }
                }
            }
            float s = 0.f;
            #pragma unroll
            for (int nt = 0; nt < 4; nt++)
                #pragma unroll
                for (int cp = 0; cp < 2; cp++)
                    s += __expf(acc[mt][nt][rp * 2 + cp] - m);

            // merge across the 4 lanes of the quad (same rows, diff cols)
            #pragma unroll
            for (int off = 1; off < 4; off <<= 1) {
                float m2 = __shfl_xor_sync(0xffffffffu, m, off);
                float s2 = __shfl_xor_sync(0xffffffffu, s, off);
                int   a2 = __shfl_xor_sync(0xffffffffu, ai, off);
                if (m2 > m || (m2 == m && a2 < ai)) ai = a2;
                float NM = fmaxf(m, m2);
                s = s * __expf(m - NM) + s2 * __expf(m2 - NM);
                m = NM;
            }
            if (qc == 0) {
                smax[wc * 128 + lrow] = m;
                ssum[wc * 128 + lrow] = s;
                sarg[wc * 128 + lrow] = ai;
            }
        }
    }
    __syncthreads();

    // ---- merge the 4 warp-cols; each warp handles 16 rows via lanes 0-15 ----
    if (lane < 16) {
        const int lrow = wid * 16 + lane;
        const int grow = rb * 128 + lrow;
        float M = -FLT_MAX, S = 0.f;
        int AI = 0;
        #pragma unroll
        for (int w = 0; w < 4; w++) {
            float v = smax[w * 128 + lrow];
            float s = ssum[w * 128 + lrow];
            if (v > M) AI = sarg[w * 128 + lrow];   // ascending w: first-idx ties
            float NM = fmaxf(M, v);
            S = S * __expf(M - NM) + s * __expf(v - NM);
            M = NM;
        }
        int pi = grow * NPART + cb;
        g_pmax[pi] = M;
        g_psum[pi] = S;
        g_pami[pi] = AI;
    }
}

// ---------------------------------------------------------------------------
// Kernel 2: finalize. 32 partials per row -> lse/argmax; reduce loss + acc.
// ---------------------------------------------------------------------------
__global__ void __launch_bounds__(256) finalize_kernel(float* __restrict__ out) {
    __shared__ float s_loss[256];
    __shared__ int   s_corr[256];
    const int tid = threadIdx.x;

    float lsum = 0.f;
    int csum = 0;
    for (int r = tid; r < M_TOT; r += 256) {
        const float* pm = &g_pmax[r * NPART];
        const float* ps = &g_psum[r * NPART];
        const int*   pa = &g_pami[r * NPART];

        float Mx = -FLT_MAX;
        #pragma unroll
        for (int t = 0; t < NPART; t++) Mx = fmaxf(Mx, pm[t]);

        float S = 0.f, bv = -FLT_MAX;
        int AI = 0;
        #pragma unroll
        for (int t = 0; t < NPART; t++) {
            float v = pm[t];
            S += ps[t] * __expf(v - Mx);
            if (v > bv) { bv = v; AI = pa[t]; }
        }
        float lse = Mx + logf(S);
        lsum += lse - g_diag[r];
        csum += (AI == r) ? 1 : 0;
    }

    s_loss[tid] = lsum;
    s_corr[tid] = csum;
    __syncthreads();
    for (int o = 128; o > 0; o >>= 1) {
        if (tid < o) {
            s_loss[tid] += s_loss[tid + o];
            s_corr[tid] += s_corr[tid + o];
        }
        __syncthreads();
    }
    if (tid == 0) {
        out[0] = s_loss[0] / (float)M_TOT;
        out[1] = 100.f * (float)s_corr[0] / (float)M_TOT;
    }
}

// ---------------------------------------------------------------------------
extern "C" void kernel_launch(void* const* d_in, const int* in_sizes, int n_in,
                              void* d_out, int out_size) {
    const float* pred = (const float*)d_in[0];
    const float* gt   = (const float*)d_in[1];

    cudaFuncSetAttribute(gemm_softmax_kernel,
                         cudaFuncAttributeMaxDynamicSharedMemorySize, SM_TOTAL);

    pack_kernel<<<2 * NPAGE, 256>>>(pred, gt);
    gemm_softmax_kernel<<<1024, 256, SM_TOTAL>>>();
    finalize_kernel<<<1, 256>>>((float*)d_out);
}

// round 6
// speedup vs baseline: 1.7483x; 1.0083x over previous
#include <cuda_runtime.h>
#include <cuda_bf16.h>
#include <cstdint>
#include <cfloat>

// ---------------- problem constants ----------------
#define M_TOT 4096          // B*N*H*W
#define C_TOT 256           // K
#define NPAGE 256           // B*N pages (each 16 m's x 256 c's)
#define NCHUNK 4            // K chunks of 64
#define NPART 32            // partials per row = 4096/128

// ---------------- scratch ----------------
__device__ __align__(16) __nv_bfloat16 g_phi[M_TOT * C_TOT];
__device__ __align__(16) __nv_bfloat16 g_plo[M_TOT * C_TOT];
__device__ __align__(16) __nv_bfloat16 g_ghi[M_TOT * C_TOT];
__device__ __align__(16) __nv_bfloat16 g_glo[M_TOT * C_TOT];
__device__ float g_diag[M_TOT];
__device__ float g_pmax[M_TOT * NPART];
__device__ float g_psum[M_TOT * NPART];
__device__ int   g_pami[M_TOT * NPART];

// ---------------- helpers ----------------
__device__ __forceinline__ uint32_t smem_u32(const void* p) {
    uint32_t a;
    asm("{ .reg .u64 t; cvta.to.shared.u64 t, %1; cvt.u32.u64 %0, t; }"
        : "=r"(a) : "l"(p));
    return a;
}
#define SWZ128(o) ((o) ^ (((o) >> 3) & 0x70))

__device__ __forceinline__ void ldsm4(uint32_t* r, uint32_t addr) {
    asm volatile("ldmatrix.sync.aligned.m8n8.x4.shared.b16 {%0,%1,%2,%3}, [%4];"
                 : "=r"(r[0]), "=r"(r[1]), "=r"(r[2]), "=r"(r[3]) : "r"(addr));
}
__device__ __forceinline__ void mma_bf16(float* d, const uint32_t* a,
                                         const uint32_t* b) {
    asm volatile(
        "mma.sync.aligned.m16n8k16.row.col.f32.bf16.bf16.f32 "
        "{%0,%1,%2,%3}, {%4,%5,%6,%7}, {%8,%9}, {%0,%1,%2,%3};"
        : "+f"(d[0]), "+f"(d[1]), "+f"(d[2]), "+f"(d[3])
        : "r"(a[0]), "r"(a[1]), "r"(a[2]), "r"(a[3]), "r"(b[0]), "r"(b[1]));
}
__device__ __forceinline__ void cp16(uint32_t smem_addr, const void* gptr) {
    asm volatile("cp.async.ca.shared.global [%0], [%1], 16;"
                 :: "r"(smem_addr), "l"(__cvta_generic_to_global(gptr)));
}
#define CP_COMMIT() asm volatile("cp.async.commit_group;" ::: "memory")
#define CP_WAIT1()  asm volatile("cp.async.wait_group 1;" ::: "memory")
#define CP_WAIT0()  asm volatile("cp.async.wait_group 0;" ::: "memory")

// smem layout: two 64KB stages + stats
#define STG_SZ  65536
#define SM_AHI  0
#define SM_ALO  16384
#define SM_BHI  32768
#define SM_BLO  49152
#define SM_SMX  131072                // float [4][128]
#define SM_SSM  (131072 + 2048)       // float [4][128]
#define SM_SAR  (131072 + 4096)       // int   [4][128]
#define SM_TOTAL (131072 + 6144)

// ---------------------------------------------------------------------------
// Kernel 0: pack (B,N,C,H,W) f32 -> row-major [M][C] bf16 hi/lo.
// ---------------------------------------------------------------------------
__global__ void __launch_bounds__(256) pack_kernel(const float* __restrict__ pred,
                                                   const float* __restrict__ gt) {
    __shared__ float s[16 * 258];
    const int tid = threadIdx.x;
    const int page = blockIdx.x & (NPAGE - 1);
    const bool is_p = blockIdx.x < NPAGE;
    const float* src = (is_p ? pred : gt) + (size_t)page * 4096;
    __nv_bfloat16* dhi = is_p ? g_phi : g_ghi;
    __nv_bfloat16* dlo = is_p ? g_plo : g_glo;

    #pragma unroll
    for (int i = tid; i < 4096; i += 256) {
        int c = i >> 4, hw = i & 15;
        s[hw * 258 + c] = src[i];
    }
    __syncthreads();
    #pragma unroll
    for (int o = tid; o < 4096; o += 256) {
        int hw = o >> 8, c = o & 255;
        float x = s[hw * 258 + c];
        __nv_bfloat16 h = __float2bfloat16(x);
        __nv_bfloat16 l = __float2bfloat16(x - __bfloat162float(h));
        size_t oi = (size_t)(page * 16 + hw) * 256 + c;
        dhi[oi] = h;
        dlo[oi] = l;
    }
}

// ---------------------------------------------------------------------------
// Kernel 1: HMMA GEMM (3-term bf16 split) + fused online row-softmax.
// CTA 128x128 tile; 8 warps as 2(row) x 4(col); warp tile 64x32.
// 1 CTA/SM (no reg cap -> no spills); 2-stage cp.async K-chunk pipeline.
// ---------------------------------------------------------------------------
__global__ void __launch_bounds__(256, 1) gemm_softmax_kernel() {
    extern __shared__ __align__(1024) char sm[];
    const uint32_t sb = smem_u32(sm);
    const int tid  = threadIdx.x;
    const int wid  = tid >> 5;
    const int lane = tid & 31;
    const int rb = blockIdx.x >> 5;   // 0..31 row block
    const int cb = blockIdx.x & 31;   // 0..31 col block

    const int wr = wid >> 2;          // 0..1 warp row (64 rows)
    const int wc = wid & 3;           // 0..3 warp col (32 cols)

    const uint32_t offA0 =
        (uint32_t)((wr * 64 + (lane & 15)) * 128 + (lane >> 4) * 16);
    const uint32_t offB0 =
        (uint32_t)((wc * 32 + ((lane >> 4) & 1) * 8 + (lane & 7)) * 128 +
                   ((lane >> 3) & 1) * 16);

    const uint4* srcAh = (const uint4*)g_phi;
    const uint4* srcAl = (const uint4*)g_plo;
    const uint4* srcBh = (const uint4*)g_ghi;
    const uint4* srcBl = (const uint4*)g_glo;

    // prefetch one K chunk into stage s
    auto prefetch = [&](int ch, int s) {
        const uint32_t base = sb + s * STG_SZ;
        #pragma unroll
        for (int t = tid; t < 1024; t += 256) {
            int r = t >> 3, sg = t & 7;
            uint32_t sw = SWZ128((uint32_t)(r * 128 + sg * 16));
            int giA = (rb * 128 + r) * 32 + ch * 8 + sg;
            int giB = (cb * 128 + r) * 32 + ch * 8 + sg;
            cp16(base + SM_AHI + sw, &srcAh[giA]);
            cp16(base + SM_ALO + sw, &srcAl[giA]);
            cp16(base + SM_BHI + sw, &srcBh[giB]);
            cp16(base + SM_BLO + sw, &srcBl[giB]);
        }
        CP_COMMIT();
    };

    float acc[4][4][4];
    #pragma unroll
    for (int a = 0; a < 4; a++)
        #pragma unroll
        for (int b = 0; b < 4; b++)
            #pragma unroll
            for (int c = 0; c < 4; c++) acc[a][b][c] = 0.f;

    prefetch(0, 0);

    for (int ch = 0; ch < NCHUNK; ch++) {
        const uint32_t stage = sb + (ch & 1) * STG_SZ;
        if (ch + 1 < NCHUNK) {
            prefetch(ch + 1, (ch + 1) & 1);
            CP_WAIT1();
        } else {
            CP_WAIT0();
        }
        __syncthreads();

        #pragma unroll
        for (int ks = 0; ks < 4; ks++) {
            const uint32_t kx = (uint32_t)(ks * 32);
            uint32_t bhi[2][4], blo[2][4];
            #pragma unroll
            for (int np = 0; np < 2; np++) {
                uint32_t ob = offB0 + np * 2048 + kx;
                ldsm4(bhi[np], stage + SM_BHI + SWZ128(ob));
                ldsm4(blo[np], stage + SM_BLO + SWZ128(ob));
            }
            #pragma unroll
            for (int mt = 0; mt < 4; mt++) {
                uint32_t oa = offA0 + mt * 2048 + kx;
                uint32_t ahi[4], alo[4];
                ldsm4(ahi, stage + SM_AHI + SWZ128(oa));
                ldsm4(alo, stage + SM_ALO + SWZ128(oa));
                #pragma unroll
                for (int nt = 0; nt < 4; nt++) {
                    const uint32_t* bh = &bhi[nt >> 1][(nt & 1) * 2];
                    const uint32_t* bl = &blo[nt >> 1][(nt & 1) * 2];
                    mma_bf16(acc[mt][nt], ahi, bh);   // hi*hi
                    mma_bf16(acc[mt][nt], ahi, bl);   // hi*lo
                    mma_bf16(acc[mt][nt], alo, bh);   // lo*hi
                }
            }
        }
        __syncthreads();
    }

    // ---- epilogue: per-thread row stats over its 8 cols ----
    const int g  = lane >> 2;
    const int qc = lane & 3;
    float* smax = (float*)(sm + SM_SMX);
    float* ssum = (float*)(sm + SM_SSM);
    int*   sarg = (int*)(sm + SM_SAR);

    #pragma unroll
    for (int mt = 0; mt < 4; mt++) {
        #pragma unroll
        for (int rp = 0; rp < 2; rp++) {
            const int lrow = wr * 64 + mt * 16 + rp * 8 + g;
            const int grow = rb * 128 + lrow;

            float m = -FLT_MAX;
            int ai = 0;
            #pragma unroll
            for (int nt = 0; nt < 4; nt++) {
                #pragma unroll
                for (int cp = 0; cp < 2; cp++) {
                    float x = acc[mt][nt][rp * 2 + cp];
                    int col = cb * 128 + wc * 32 + nt * 8 + qc * 2 + cp;
                    if (col == grow) g_diag[grow] = x;
                    if (x > m) { m = x; ai = col; }
                }
            }
            float s = 0.f;
            #pragma unroll
            for (int nt = 0; nt < 4; nt++)
                #pragma unroll
                for (int cp = 0; cp < 2; cp++)
                    s += __expf(acc[mt][nt][rp * 2 + cp] - m);

            #pragma unroll
            for (int off = 1; off < 4; off <<= 1) {
                float m2 = __shfl_xor_sync(0xffffffffu, m, off);
                float s2 = __shfl_xor_sync(0xffffffffu, s, off);
                int   a2 = __shfl_xor_sync(0xffffffffu, ai, off);
                if (m2 > m || (m2 == m && a2 < ai)) ai = a2;
                float NM = fmaxf(m, m2);
                s = s * __expf(m - NM) + s2 * __expf(m2 - NM);
                m = NM;
            }
            if (qc == 0) {
                smax[wc * 128 + lrow] = m;
                ssum[wc * 128 + lrow] = s;
                sarg[wc * 128 + lrow] = ai;
            }
        }
    }
    __syncthreads();

    if (lane < 16) {
        const int lrow = wid * 16 + lane;
        const int grow = rb * 128 + lrow;
        float M = -FLT_MAX, S = 0.f;
        int AI = 0;
        #pragma unroll
        for (int w = 0; w < 4; w++) {
            float v = smax[w * 128 + lrow];
            float s = ssum[w * 128 + lrow];
            if (v > M) AI = sarg[w * 128 + lrow];   // ascending w: first-idx ties
            float NM = fmaxf(M, v);
            S = S * __expf(M - NM) + s * __expf(v - NM);
            M = NM;
        }
        int pi = grow * NPART + cb;
        g_pmax[pi] = M;
        g_psum[pi] = S;
        g_pami[pi] = AI;
    }
}

// ---------------------------------------------------------------------------
// Kernel 2: finalize. 32 partials per row -> lse/argmax; reduce loss + acc.
// ---------------------------------------------------------------------------
__global__ void __launch_bounds__(256) finalize_kernel(float* __restrict__ out) {
    __shared__ float s_loss[256];
    __shared__ int   s_corr[256];
    const int tid = threadIdx.x;

    float lsum = 0.f;
    int csum = 0;
    for (int r = tid; r < M_TOT; r += 256) {
        const float* pm = &g_pmax[r * NPART];
        const float* ps = &g_psum[r * NPART];
        const int*   pa = &g_pami[r * NPART];

        float Mx = -FLT_MAX;
        #pragma unroll
        for (int t = 0; t < NPART; t++) Mx = fmaxf(Mx, pm[t]);

        float S = 0.f, bv = -FLT_MAX;
        int AI = 0;
        #pragma unroll
        for (int t = 0; t < NPART; t++) {
            float v = pm[t];
            S += ps[t] * __expf(v - Mx);
            if (v > bv) { bv = v; AI = pa[t]; }
        }
        float lse = Mx + logf(S);
        lsum += lse - g_diag[r];
        csum += (AI == r) ? 1 : 0;
    }

    s_loss[tid] = lsum;
    s_corr[tid] = csum;
    __syncthreads();
    for (int o = 128; o > 0; o >>= 1) {
        if (tid < o) {
            s_loss[tid] += s_loss[tid + o];
            s_corr[tid] += s_corr[tid + o];
        }
        __syncthreads();
    }
    if (tid == 0) {
        out[0] = s_loss[0] / (float)M_TOT;
        out[1] = 100.f * (float)s_corr[0] / (float)M_TOT;
    }
}

// ---------------------------------------------------------------------------
extern "C" void kernel_launch(void* const* d_in, const int* in_sizes, int n_in,
                              void* d_out, int out_size) {
    const float* pred = (const float*)d_in[0];
    const float* gt   = (const float*)d_in[1];

    cudaFuncSetAttribute(gemm_softmax_kernel,
                         cudaFuncAttributeMaxDynamicSharedMemorySize, SM_TOTAL);

    pack_kernel<<<2 * NPAGE, 256>>>(pred, gt);
    gemm_softmax_kernel<<<1024, 256, SM_TOTAL>>>();
    finalize_kernel<<<1, 256>>>((float*)d_out);
}

// round 7
// speedup vs baseline: 2.0767x; 1.1878x over previous
#include <cuda_runtime.h>
#include <cuda_fp16.h>
#include <cstdint>
#include <cfloat>

// ---------------- problem constants ----------------
#define M_TOT 4096          // B*N*H*W
#define C_TOT 256           // K
#define NPAGE 256           // B*N pages (each 16 m's x 256 c's)
#define NCHUNK 4            // K chunks of 64
#define NPART 32            // partials per row = 4096/128

// ---------------- scratch ----------------
__device__ __align__(16) __half g_p16[M_TOT * C_TOT];
__device__ __align__(16) __half g_g16[M_TOT * C_TOT];
__device__ float g_diag[M_TOT];
__device__ float g_pmax[M_TOT * NPART];
__device__ float g_psum[M_TOT * NPART];
__device__ int   g_pami[M_TOT * NPART];

// ---------------- helpers ----------------
__device__ __forceinline__ uint32_t smem_u32(const void* p) {
    uint32_t a;
    asm("{ .reg .u64 t; cvta.to.shared.u64 t, %1; cvt.u32.u64 %0, t; }"
        : "=r"(a) : "l"(p));
    return a;
}
#define SWZ128(o) ((o) ^ (((o) >> 3) & 0x70))

__device__ __forceinline__ void ldsm4(uint32_t* r, uint32_t addr) {
    asm volatile("ldmatrix.sync.aligned.m8n8.x4.shared.b16 {%0,%1,%2,%3}, [%4];"
                 : "=r"(r[0]), "=r"(r[1]), "=r"(r[2]), "=r"(r[3]) : "r"(addr));
}
__device__ __forceinline__ void mma_fp16(float* d, const uint32_t* a,
                                         const uint32_t* b) {
    asm volatile(
        "mma.sync.aligned.m16n8k16.row.col.f32.f16.f16.f32 "
        "{%0,%1,%2,%3}, {%4,%5,%6,%7}, {%8,%9}, {%0,%1,%2,%3};"
        : "+f"(d[0]), "+f"(d[1]), "+f"(d[2]), "+f"(d[3])
        : "r"(a[0]), "r"(a[1]), "r"(a[2]), "r"(a[3]), "r"(b[0]), "r"(b[1]));
}
__device__ __forceinline__ void cp16(uint32_t smem_addr, const void* gptr) {
    asm volatile("cp.async.ca.shared.global [%0], [%1], 16;"
                 :: "r"(smem_addr), "l"(__cvta_generic_to_global(gptr)));
}
#define CP_COMMIT() asm volatile("cp.async.commit_group;" ::: "memory")
#define CP_WAIT1()  asm volatile("cp.async.wait_group 1;" ::: "memory")
#define CP_WAIT0()  asm volatile("cp.async.wait_group 0;" ::: "memory")

// smem layout: two 32KB stages (A 16KB + B 16KB) + stats
#define STG_SZ  32768
#define SM_A    0
#define SM_B    16384
#define SM_SMX  65536                 // float [4][128]
#define SM_SSM  (65536 + 2048)        // float [4][128]
#define SM_SAR  (65536 + 4096)        // int   [4][128]
#define SM_TOTAL (65536 + 6144)

// ---------------------------------------------------------------------------
// Kernel 0: pack (B,N,C,H,W) f32 -> row-major [M][C] fp16.
// ---------------------------------------------------------------------------
__global__ void __launch_bounds__(256) pack_kernel(const float* __restrict__ pred,
                                                   const float* __restrict__ gt) {
    __shared__ float s[16 * 258];
    const int tid = threadIdx.x;
    const int page = blockIdx.x & (NPAGE - 1);
    const bool is_p = blockIdx.x < NPAGE;
    const float* src = (is_p ? pred : gt) + (size_t)page * 4096;
    __half* dst = is_p ? g_p16 : g_g16;

    #pragma unroll
    for (int i = tid; i < 4096; i += 256) {
        int c = i >> 4, hw = i & 15;
        s[hw * 258 + c] = src[i];
    }
    __syncthreads();
    #pragma unroll
    for (int o = tid; o < 4096; o += 256) {
        int hw = o >> 8, c = o & 255;
        dst[(size_t)(page * 16 + hw) * 256 + c] = __float2half(s[hw * 258 + c]);
    }
}

// ---------------------------------------------------------------------------
// Kernel 1: fp16 HMMA GEMM + fused online row-softmax.
// CTA 128x128 tile; 8 warps as 2(row) x 4(col); warp tile 64x32.
// 2-stage cp.async K-chunk (64) pipeline.
// ---------------------------------------------------------------------------
__global__ void __launch_bounds__(256, 1) gemm_softmax_kernel() {
    extern __shared__ __align__(1024) char sm[];
    const uint32_t sb = smem_u32(sm);
    const int tid  = threadIdx.x;
    const int wid  = tid >> 5;
    const int lane = tid & 31;
    const int rb = blockIdx.x >> 5;   // 0..31 row block
    const int cb = blockIdx.x & 31;   // 0..31 col block

    const int wr = wid >> 2;          // 0..1 warp row (64 rows)
    const int wc = wid & 3;           // 0..3 warp col (32 cols)

    const uint32_t offA0 =
        (uint32_t)((wr * 64 + (lane & 15)) * 128 + (lane >> 4) * 16);
    const uint32_t offB0 =
        (uint32_t)((wc * 32 + ((lane >> 4) & 1) * 8 + (lane & 7)) * 128 +
                   ((lane >> 3) & 1) * 16);

    const uint4* srcA = (const uint4*)g_p16;
    const uint4* srcB = (const uint4*)g_g16;

    // prefetch one K chunk (64 k) into stage s
    auto prefetch = [&](int ch, int s) {
        const uint32_t base = sb + s * STG_SZ;
        #pragma unroll
        for (int t = tid; t < 1024; t += 256) {
            int r = t >> 3, sg = t & 7;
            uint32_t sw = SWZ128((uint32_t)(r * 128 + sg * 16));
            int giA = (rb * 128 + r) * 32 + ch * 8 + sg;
            int giB = (cb * 128 + r) * 32 + ch * 8 + sg;
            cp16(base + SM_A + sw, &srcA[giA]);
            cp16(base + SM_B + sw, &srcB[giB]);
        }
        CP_COMMIT();
    };

    float acc[4][4][4];
    #pragma unroll
    for (int a = 0; a < 4; a++)
        #pragma unroll
        for (int b = 0; b < 4; b++)
            #pragma unroll
            for (int c = 0; c < 4; c++) acc[a][b][c] = 0.f;

    prefetch(0, 0);

    for (int ch = 0; ch < NCHUNK; ch++) {
        const uint32_t stage = sb + (ch & 1) * STG_SZ;
        if (ch + 1 < NCHUNK) {
            prefetch(ch + 1, (ch + 1) & 1);
            CP_WAIT1();
        } else {
            CP_WAIT0();
        }
        __syncthreads();

        #pragma unroll
        for (int ks = 0; ks < 4; ks++) {
            const uint32_t kx = (uint32_t)(ks * 32);
            uint32_t bf[2][4];
            #pragma unroll
            for (int np = 0; np < 2; np++) {
                uint32_t ob = offB0 + np * 2048 + kx;
                ldsm4(bf[np], stage + SM_B + SWZ128(ob));
            }
            #pragma unroll
            for (int mt = 0; mt < 4; mt++) {
                uint32_t oa = offA0 + mt * 2048 + kx;
                uint32_t af[4];
                ldsm4(af, stage + SM_A + SWZ128(oa));
                #pragma unroll
                for (int nt = 0; nt < 4; nt++)
                    mma_fp16(acc[mt][nt], af, &bf[nt >> 1][(nt & 1) * 2]);
            }
        }
        __syncthreads();
    }

    // ---- epilogue: per-thread row stats over its 8 cols ----
    const int g  = lane >> 2;
    const int qc = lane & 3;
    float* smax = (float*)(sm + SM_SMX);
    float* ssum = (float*)(sm + SM_SSM);
    int*   sarg = (int*)(sm + SM_SAR);

    #pragma unroll
    for (int mt = 0; mt < 4; mt++) {
        #pragma unroll
        for (int rp = 0; rp < 2; rp++) {
            const int lrow = wr * 64 + mt * 16 + rp * 8 + g;
            const int grow = rb * 128 + lrow;

            float m = -FLT_MAX;
            int ai = 0;
            #pragma unroll
            for (int nt = 0; nt < 4; nt++) {
                #pragma unroll
                for (int cp = 0; cp < 2; cp++) {
                    float x = acc[mt][nt][rp * 2 + cp];
                    int col = cb * 128 + wc * 32 + nt * 8 + qc * 2 + cp;
                    if (col == grow) g_diag[grow] = x;
                    if (x > m) { m = x; ai = col; }
                }
            }
            float s = 0.f;
            #pragma unroll
            for (int nt = 0; nt < 4; nt++)
                #pragma unroll
                for (int cp = 0; cp < 2; cp++)
                    s += __expf(acc[mt][nt][rp * 2 + cp] - m);

            #pragma unroll
            for (int off = 1; off < 4; off <<= 1) {
                float m2 = __shfl_xor_sync(0xffffffffu, m, off);
                float s2 = __shfl_xor_sync(0xffffffffu, s, off);
                int   a2 = __shfl_xor_sync(0xffffffffu, ai, off);
                if (m2 > m || (m2 == m && a2 < ai)) ai = a2;
                float NM = fmaxf(m, m2);
                s = s * __expf(m - NM) + s2 * __expf(m2 - NM);
                m = NM;
            }
            if (qc == 0) {
                smax[wc * 128 + lrow] = m;
                ssum[wc * 128 + lrow] = s;
                sarg[wc * 128 + lrow] = ai;
            }
        }
    }
    __syncthreads();

    if (lane < 16) {
        const int lrow = wid * 16 + lane;
        const int grow = rb * 128 + lrow;
        float M = -FLT_MAX, S = 0.f;
        int AI = 0;
        #pragma unroll
        for (int w = 0; w < 4; w++) {
            float v = smax[w * 128 + lrow];
            float s = ssum[w * 128 + lrow];
            if (v > M) AI = sarg[w * 128 + lrow];   // ascending w: first-idx ties
            float NM = fmaxf(M, v);
            S = S * __expf(M - NM) + s * __expf(v - NM);
            M = NM;
        }
        int pi = grow * NPART + cb;
        g_pmax[pi] = M;
        g_psum[pi] = S;
        g_pami[pi] = AI;
    }
}

// ---------------------------------------------------------------------------
// Kernel 2: finalize. 32 partials per row -> lse/argmax; reduce loss + acc.
// ---------------------------------------------------------------------------
__global__ void __launch_bounds__(256) finalize_kernel(float* __restrict__ out) {
    __shared__ float s_loss[256];
    __shared__ int   s_corr[256];
    const int tid = threadIdx.x;

    float lsum = 0.f;
    int csum = 0;
    for (int r = tid; r < M_TOT; r += 256) {
        const float* pm = &g_pmax[r * NPART];
        const float* ps = &g_psum[r * NPART];
        const int*   pa = &g_pami[r * NPART];

        float Mx = -FLT_MAX;
        #pragma unroll
        for (int t = 0; t < NPART; t++) Mx = fmaxf(Mx, pm[t]);

        float S = 0.f, bv = -FLT_MAX;
        int AI = 0;
        #pragma unroll
        for (int t = 0; t < NPART; t++) {
            float v = pm[t];
            S += ps[t] * __expf(v - Mx);
            if (v > bv) { bv = v; AI = pa[t]; }
        }
        float lse = Mx + logf(S);
        lsum += lse - g_diag[r];
        csum += (AI == r) ? 1 : 0;
    }

    s_loss[tid] = lsum;
    s_corr[tid] = csum;
    __syncthreads();
    for (int o = 128; o > 0; o >>= 1) {
        if (tid < o) {
            s_loss[tid] += s_loss[tid + o];
            s_corr[tid] += s_corr[tid + o];
        }
        __syncthreads();
    }
    if (tid == 0) {
        out[0] = s_loss[0] / (float)M_TOT;
        out[1] = 100.f * (float)s_corr[0] / (float)M_TOT;
    }
}

// ---------------------------------------------------------------------------
extern "C" void kernel_launch(void* const* d_in, const int* in_sizes, int n_in,
                              void* d_out, int out_size) {
    const float* pred = (const float*)d_in[0];
    const float* gt   = (const float*)d_in[1];

    cudaFuncSetAttribute(gemm_softmax_kernel,
                         cudaFuncAttributeMaxDynamicSharedMemorySize, SM_TOTAL);

    pack_kernel<<<2 * NPAGE, 256>>>(pred, gt);
    gemm_softmax_kernel<<<1024, 256, SM_TOTAL>>>();
    finalize_kernel<<<1, 256>>>((float*)d_out);
}

// round 8
// speedup vs baseline: 7.1552x; 3.4454x over previous
#include <cuda_runtime.h>
#include <cuda_fp16.h>
#include <cstdint>
#include <cfloat>

// ---------------- problem constants ----------------
#define M_TOT 4096          // B*N*H*W
#define C_TOT 256           // K
#define NPAGE 256           // B*N pages (each 16 m's x 256 c's)
#define NCHUNK 4            // K chunks of 64
#define NPART 32            // partials per row = 4096/128
#define NFBLK 16            // finalize blocks

// ---------------- scratch ----------------
__device__ __align__(16) __half g_p16[M_TOT * C_TOT];
__device__ __align__(16) __half g_g16[M_TOT * C_TOT];
__device__ float g_diag[M_TOT];
// transposed partials: [tile][row] -> coalesced on both write and read
__device__ float g_pmax[NPART * M_TOT];
__device__ float g_psum[NPART * M_TOT];
__device__ int   g_pami[NPART * M_TOT];
__device__ float g_blk_loss[NFBLK];
__device__ int   g_blk_corr[NFBLK];

// ---------------- helpers ----------------
__device__ __forceinline__ uint32_t smem_u32(const void* p) {
    uint32_t a;
    asm("{ .reg .u64 t; cvta.to.shared.u64 t, %1; cvt.u32.u64 %0, t; }"
        : "=r"(a) : "l"(p));
    return a;
}
#define SWZ128(o) ((o) ^ (((o) >> 3) & 0x70))

__device__ __forceinline__ void ldsm4(uint32_t* r, uint32_t addr) {
    asm volatile("ldmatrix.sync.aligned.m8n8.x4.shared.b16 {%0,%1,%2,%3}, [%4];"
                 : "=r"(r[0]), "=r"(r[1]), "=r"(r[2]), "=r"(r[3]) : "r"(addr));
}
__device__ __forceinline__ void mma_fp16(float* d, const uint32_t* a,
                                         const uint32_t* b) {
    asm volatile(
        "mma.sync.aligned.m16n8k16.row.col.f32.f16.f16.f32 "
        "{%0,%1,%2,%3}, {%4,%5,%6,%7}, {%8,%9}, {%0,%1,%2,%3};"
        : "+f"(d[0]), "+f"(d[1]), "+f"(d[2]), "+f"(d[3])
        : "r"(a[0]), "r"(a[1]), "r"(a[2]), "r"(a[3]), "r"(b[0]), "r"(b[1]));
}
__device__ __forceinline__ void cp16(uint32_t smem_addr, const void* gptr) {
    asm volatile("cp.async.ca.shared.global [%0], [%1], 16;"
                 :: "r"(smem_addr), "l"(__cvta_generic_to_global(gptr)));
}
#define CP_COMMIT() asm volatile("cp.async.commit_group;" ::: "memory")
#define CP_WAIT1()  asm volatile("cp.async.wait_group 1;" ::: "memory")
#define CP_WAIT0()  asm volatile("cp.async.wait_group 0;" ::: "memory")

// smem layout: two 32KB stages (A 16KB + B 16KB) + stats
#define STG_SZ  32768
#define SM_A    0
#define SM_B    16384
#define SM_SMX  65536                 // float [4][128]
#define SM_SSM  (65536 + 2048)        // float [4][128]
#define SM_SAR  (65536 + 4096)        // int   [4][128]
#define SM_TOTAL (65536 + 6144)

// ---------------------------------------------------------------------------
// Kernel 0: pack (B,N,C,H,W) f32 -> row-major [M][C] fp16.
// ---------------------------------------------------------------------------
__global__ void __launch_bounds__(256) pack_kernel(const float* __restrict__ pred,
                                                   const float* __restrict__ gt) {
    __shared__ float s[16 * 258];
    const int tid = threadIdx.x;
    const int page = blockIdx.x & (NPAGE - 1);
    const bool is_p = blockIdx.x < NPAGE;
    const float* src = (is_p ? pred : gt) + (size_t)page * 4096;
    __half* dst = is_p ? g_p16 : g_g16;

    #pragma unroll
    for (int i = tid; i < 4096; i += 256) {
        int c = i >> 4, hw = i & 15;
        s[hw * 258 + c] = src[i];
    }
    __syncthreads();
    #pragma unroll
    for (int o = tid; o < 4096; o += 256) {
        int hw = o >> 8, c = o & 255;
        dst[(size_t)(page * 16 + hw) * 256 + c] = __float2half(s[hw * 258 + c]);
    }
}

// ---------------------------------------------------------------------------
// Kernel 1: fp16 HMMA GEMM + fused online row-softmax.
// CTA 128x128 tile; 8 warps as 2(row) x 4(col); warp tile 64x32.
// ---------------------------------------------------------------------------
__global__ void __launch_bounds__(256, 1) gemm_softmax_kernel() {
    extern __shared__ __align__(1024) char sm[];
    const uint32_t sb = smem_u32(sm);
    const int tid  = threadIdx.x;
    const int wid  = tid >> 5;
    const int lane = tid & 31;
    const int rb = blockIdx.x >> 5;   // 0..31 row block
    const int cb = blockIdx.x & 31;   // 0..31 col block

    const int wr = wid >> 2;          // 0..1 warp row (64 rows)
    const int wc = wid & 3;           // 0..3 warp col (32 cols)

    const uint32_t offA0 =
        (uint32_t)((wr * 64 + (lane & 15)) * 128 + (lane >> 4) * 16);
    const uint32_t offB0 =
        (uint32_t)((wc * 32 + ((lane >> 4) & 1) * 8 + (lane & 7)) * 128 +
                   ((lane >> 3) & 1) * 16);

    const uint4* srcA = (const uint4*)g_p16;
    const uint4* srcB = (const uint4*)g_g16;

    auto prefetch = [&](int ch, int s) {
        const uint32_t base = sb + s * STG_SZ;
        #pragma unroll
        for (int t = tid; t < 1024; t += 256) {
            int r = t >> 3, sg = t & 7;
            uint32_t sw = SWZ128((uint32_t)(r * 128 + sg * 16));
            int giA = (rb * 128 + r) * 32 + ch * 8 + sg;
            int giB = (cb * 128 + r) * 32 + ch * 8 + sg;
            cp16(base + SM_A + sw, &srcA[giA]);
            cp16(base + SM_B + sw, &srcB[giB]);
        }
        CP_COMMIT();
    };

    float acc[4][4][4];
    #pragma unroll
    for (int a = 0; a < 4; a++)
        #pragma unroll
        for (int b = 0; b < 4; b++)
            #pragma unroll
            for (int c = 0; c < 4; c++) acc[a][b][c] = 0.f;

    prefetch(0, 0);

    for (int ch = 0; ch < NCHUNK; ch++) {
        const uint32_t stage = sb + (ch & 1) * STG_SZ;
        if (ch + 1 < NCHUNK) {
            prefetch(ch + 1, (ch + 1) & 1);
            CP_WAIT1();
        } else {
            CP_WAIT0();
        }
        __syncthreads();

        #pragma unroll
        for (int ks = 0; ks < 4; ks++) {
            const uint32_t kx = (uint32_t)(ks * 32);
            uint32_t bf[2][4];
            #pragma unroll
            for (int np = 0; np < 2; np++) {
                uint32_t ob = offB0 + np * 2048 + kx;
                ldsm4(bf[np], stage + SM_B + SWZ128(ob));
            }
            #pragma unroll
            for (int mt = 0; mt < 4; mt++) {
                uint32_t oa = offA0 + mt * 2048 + kx;
                uint32_t af[4];
                ldsm4(af, stage + SM_A + SWZ128(oa));
                #pragma unroll
                for (int nt = 0; nt < 4; nt++)
                    mma_fp16(acc[mt][nt], af, &bf[nt >> 1][(nt & 1) * 2]);
            }
        }
        __syncthreads();
    }

    // ---- epilogue: per-thread row stats over its 8 cols ----
    const int g  = lane >> 2;
    const int qc = lane & 3;
    float* smax = (float*)(sm + SM_SMX);
    float* ssum = (float*)(sm + SM_SSM);
    int*   sarg = (int*)(sm + SM_SAR);

    #pragma unroll
    for (int mt = 0; mt < 4; mt++) {
        #pragma unroll
        for (int rp = 0; rp < 2; rp++) {
            const int lrow = wr * 64 + mt * 16 + rp * 8 + g;
            const int grow = rb * 128 + lrow;

            float m = -FLT_MAX;
            int ai = 0;
            #pragma unroll
            for (int nt = 0; nt < 4; nt++) {
                #pragma unroll
                for (int cp = 0; cp < 2; cp++) {
                    float x = acc[mt][nt][rp * 2 + cp];
                    int col = cb * 128 + wc * 32 + nt * 8 + qc * 2 + cp;
                    if (col == grow) g_diag[grow] = x;
                    if (x > m) { m = x; ai = col; }
                }
            }
            float s = 0.f;
            #pragma unroll
            for (int nt = 0; nt < 4; nt++)
                #pragma unroll
                for (int cp = 0; cp < 2; cp++)
                    s += __expf(acc[mt][nt][rp * 2 + cp] - m);

            #pragma unroll
            for (int off = 1; off < 4; off <<= 1) {
                float m2 = __shfl_xor_sync(0xffffffffu, m, off);
                float s2 = __shfl_xor_sync(0xffffffffu, s, off);
                int   a2 = __shfl_xor_sync(0xffffffffu, ai, off);
                if (m2 > m || (m2 == m && a2 < ai)) ai = a2;
                float NM = fmaxf(m, m2);
                s = s * __expf(m - NM) + s2 * __expf(m2 - NM);
                m = NM;
            }
            if (qc == 0) {
                smax[wc * 128 + lrow] = m;
                ssum[wc * 128 + lrow] = s;
                sarg[wc * 128 + lrow] = ai;
            }
        }
    }
    __syncthreads();

    // ---- merge 4 warp-cols; coalesced transposed write [cb][row] ----
    if (lane < 16) {
        const int lrow = wid * 16 + lane;
        const int grow = rb * 128 + lrow;
        float M = -FLT_MAX, S = 0.f;
        int AI = 0;
        #pragma unroll
        for (int w = 0; w < 4; w++) {
            float v = smax[w * 128 + lrow];
            float s = ssum[w * 128 + lrow];
            if (v > M) AI = sarg[w * 128 + lrow];   // ascending w: first-idx ties
            float NM = fmaxf(M, v);
            S = S * __expf(M - NM) + s * __expf(v - NM);
            M = NM;
        }
        int pi = cb * M_TOT + grow;
        g_pmax[pi] = M;
        g_psum[pi] = S;
        g_pami[pi] = AI;
    }
}

// ---------------------------------------------------------------------------
// Kernel 2a: per-row reduce (1 row per thread, coalesced) -> 16 block partials.
// ---------------------------------------------------------------------------
__global__ void __launch_bounds__(256) finalize_rows_kernel() {
    __shared__ float s_loss[256];
    __shared__ int   s_corr[256];
    const int tid = threadIdx.x;
    const int r = blockIdx.x * 256 + tid;

    float Mx = -FLT_MAX;
    #pragma unroll
    for (int t = 0; t < NPART; t++) Mx = fmaxf(Mx, g_pmax[t * M_TOT + r]);

    float S = 0.f, bv = -FLT_MAX;
    int AI = 0;
    #pragma unroll
    for (int t = 0; t < NPART; t++) {
        float v = g_pmax[t * M_TOT + r];
        S += g_psum[t * M_TOT + r] * __expf(v - Mx);
        if (v > bv) { bv = v; AI = g_pami[t * M_TOT + r]; }  // first-idx ties
    }
    float lse = Mx + logf(S);

    s_loss[tid] = lse - g_diag[r];
    s_corr[tid] = (AI == r) ? 1 : 0;
    __syncthreads();
    for (int o = 128; o > 0; o >>= 1) {
        if (tid < o) {
            s_loss[tid] += s_loss[tid + o];
            s_corr[tid] += s_corr[tid + o];
        }
        __syncthreads();
    }
    if (tid == 0) {
        g_blk_loss[blockIdx.x] = s_loss[0];
        g_blk_corr[blockIdx.x] = s_corr[0];
    }
}

// ---------------------------------------------------------------------------
// Kernel 2b: sum 16 partials -> (loss, acc). Deterministic fixed order.
// ---------------------------------------------------------------------------
__global__ void finalize_out_kernel(float* __restrict__ out) {
    if (threadIdx.x == 0) {
        float L = 0.f;
        int Cc = 0;
        #pragma unroll
        for (int i = 0; i < NFBLK; i++) {
            L += g_blk_loss[i];
            Cc += g_blk_corr[i];
        }
        out[0] = L / (float)M_TOT;
        out[1] = 100.f * (float)Cc / (float)M_TOT;
    }
}

// ---------------------------------------------------------------------------
extern "C" void kernel_launch(void* const* d_in, const int* in_sizes, int n_in,
                              void* d_out, int out_size) {
    const float* pred = (const float*)d_in[0];
    const float* gt   = (const float*)d_in[1];

    cudaFuncSetAttribute(gemm_softmax_kernel,
                         cudaFuncAttributeMaxDynamicSharedMemorySize, SM_TOTAL);

    pack_kernel<<<2 * NPAGE, 256>>>(pred, gt);
    gemm_softmax_kernel<<<1024, 256, SM_TOTAL>>>();
    finalize_rows_kernel<<<NFBLK, 256>>>();
    finalize_out_kernel<<<1, 32>>>((float*)d_out);
}

// round 9
// speedup vs baseline: 7.4284x; 1.0382x over previous
#include <cuda_runtime.h>
#include <cuda_fp16.h>
#include <cstdint>
#include <cfloat>

// ---------------- problem constants ----------------
#define M_TOT 4096          // B*N*H*W
#define C_TOT 256           // K
#define NPAGE 256           // B*N pages (each 16 m's x 256 c's)
#define NCHUNK 4            // K chunks of 64
#define NPART 32            // partials per row = 4096/128
#define NFBLK 16            // finalize blocks

// ---------------- scratch ----------------
__device__ __align__(16) __half g_p16[M_TOT * C_TOT];
__device__ __align__(16) __half g_g16[M_TOT * C_TOT];
__device__ float g_diag[M_TOT];
// transposed partials: [tile][row] -> coalesced write and read
__device__ float g_pmax[NPART * M_TOT];
__device__ float g_psum[NPART * M_TOT];
__device__ int   g_pami[NPART * M_TOT];
__device__ float g_blk_loss[NFBLK];
__device__ int   g_blk_corr[NFBLK];
__device__ unsigned g_done = 0;    // arrival counter (reset by last block)

// ---------------- helpers ----------------
__device__ __forceinline__ uint32_t smem_u32(const void* p) {
    uint32_t a;
    asm("{ .reg .u64 t; cvta.to.shared.u64 t, %1; cvt.u32.u64 %0, t; }"
        : "=r"(a) : "l"(p));
    return a;
}
#define SWZ128(o) ((o) ^ (((o) >> 3) & 0x70))

__device__ __forceinline__ void ldsm4(uint32_t* r, uint32_t addr) {
    asm volatile("ldmatrix.sync.aligned.m8n8.x4.shared.b16 {%0,%1,%2,%3}, [%4];"
                 : "=r"(r[0]), "=r"(r[1]), "=r"(r[2]), "=r"(r[3]) : "r"(addr));
}
__device__ __forceinline__ void mma_fp16(float* d, const uint32_t* a,
                                         const uint32_t* b) {
    asm volatile(
        "mma.sync.aligned.m16n8k16.row.col.f32.f16.f16.f32 "
        "{%0,%1,%2,%3}, {%4,%5,%6,%7}, {%8,%9}, {%0,%1,%2,%3};"
        : "+f"(d[0]), "+f"(d[1]), "+f"(d[2]), "+f"(d[3])
        : "r"(a[0]), "r"(a[1]), "r"(a[2]), "r"(a[3]), "r"(b[0]), "r"(b[1]));
}
__device__ __forceinline__ void cp16(uint32_t smem_addr, const void* gptr) {
    asm volatile("cp.async.ca.shared.global [%0], [%1], 16;"
                 :: "r"(smem_addr), "l"(__cvta_generic_to_global(gptr)));
}
#define CP_COMMIT() asm volatile("cp.async.commit_group;" ::: "memory")
#define CP_WAIT1()  asm volatile("cp.async.wait_group 1;" ::: "memory")
#define CP_WAIT0()  asm volatile("cp.async.wait_group 0;" ::: "memory")

// smem layout: two 32KB stages (A 16KB + B 16KB) + stats
#define STG_SZ  32768
#define SM_A    0
#define SM_B    16384
#define SM_SMX  65536                 // float [4][128]
#define SM_SSM  (65536 + 2048)        // float [4][128]
#define SM_SAR  (65536 + 4096)        // int   [4][128]
#define SM_TOTAL (65536 + 6144)

// ---------------------------------------------------------------------------
// Kernel 0: pack (B,N,C,H,W) f32 -> row-major [M][C] fp16 (half2 stores).
// ---------------------------------------------------------------------------
__global__ void __launch_bounds__(256) pack_kernel(const float* __restrict__ pred,
                                                   const float* __restrict__ gt) {
    __shared__ float s[16 * 258];
    const int tid = threadIdx.x;
    const int page = blockIdx.x & (NPAGE - 1);
    const bool is_p = blockIdx.x < NPAGE;
    const float* src = (is_p ? pred : gt) + (size_t)page * 4096;
    __half2* dst = (__half2*)(is_p ? g_p16 : g_g16);

    #pragma unroll
    for (int i = tid; i < 4096; i += 256) {
        int c = i >> 4, hw = i & 15;
        s[hw * 258 + c] = src[i];
    }
    __syncthreads();
    #pragma unroll
    for (int o = tid; o < 2048; o += 256) {   // 2048 half2 per page
        int hw = o >> 7, c = (o & 127) * 2;
        __half2 v = __floats2half2_rn(s[hw * 258 + c], s[hw * 258 + c + 1]);
        dst[(size_t)(page * 16 + hw) * 128 + (o & 127)] = v;
    }
}

// ---------------------------------------------------------------------------
// Kernel 1: fp16 HMMA GEMM + fused online row-softmax.
// CTA 128x128 tile; 8 warps as 2(row) x 4(col); warp tile 64x32.
// 2 CTAs/SM (fp16 single-term fits 128 regs); 2-stage cp.async pipeline.
// ---------------------------------------------------------------------------
__global__ void __launch_bounds__(256, 2) gemm_softmax_kernel() {
    extern __shared__ __align__(1024) char sm[];
    const uint32_t sb = smem_u32(sm);
    const int tid  = threadIdx.x;
    const int wid  = tid >> 5;
    const int lane = tid & 31;
    const int rb = blockIdx.x >> 5;   // 0..31 row block
    const int cb = blockIdx.x & 31;   // 0..31 col block

    const int wr = wid >> 2;          // 0..1 warp row (64 rows)
    const int wc = wid & 3;           // 0..3 warp col (32 cols)

    const uint32_t offA0 =
        (uint32_t)((wr * 64 + (lane & 15)) * 128 + (lane >> 4) * 16);
    const uint32_t offB0 =
        (uint32_t)((wc * 32 + ((lane >> 4) & 1) * 8 + (lane & 7)) * 128 +
                   ((lane >> 3) & 1) * 16);

    const uint4* srcA = (const uint4*)g_p16;
    const uint4* srcB = (const uint4*)g_g16;

    auto prefetch = [&](int ch, int s) {
        const uint32_t base = sb + s * STG_SZ;
        #pragma unroll
        for (int t = tid; t < 1024; t += 256) {
            int r = t >> 3, sg = t & 7;
            uint32_t sw = SWZ128((uint32_t)(r * 128 + sg * 16));
            int giA = (rb * 128 + r) * 32 + ch * 8 + sg;
            int giB = (cb * 128 + r) * 32 + ch * 8 + sg;
            cp16(base + SM_A + sw, &srcA[giA]);
            cp16(base + SM_B + sw, &srcB[giB]);
        }
        CP_COMMIT();
    };

    float acc[4][4][4];
    #pragma unroll
    for (int a = 0; a < 4; a++)
        #pragma unroll
        for (int b = 0; b < 4; b++)
            #pragma unroll
            for (int c = 0; c < 4; c++) acc[a][b][c] = 0.f;

    prefetch(0, 0);

    for (int ch = 0; ch < NCHUNK; ch++) {
        const uint32_t stage = sb + (ch & 1) * STG_SZ;
        if (ch + 1 < NCHUNK) {
            prefetch(ch + 1, (ch + 1) & 1);
            CP_WAIT1();
        } else {
            CP_WAIT0();
        }
        __syncthreads();

        #pragma unroll
        for (int ks = 0; ks < 4; ks++) {
            const uint32_t kx = (uint32_t)(ks * 32);
            uint32_t bf[2][4];
            #pragma unroll
            for (int np = 0; np < 2; np++) {
                uint32_t ob = offB0 + np * 2048 + kx;
                ldsm4(bf[np], stage + SM_B + SWZ128(ob));
            }
            #pragma unroll
            for (int mt = 0; mt < 4; mt++) {
                uint32_t oa = offA0 + mt * 2048 + kx;
                uint32_t af[4];
                ldsm4(af, stage + SM_A + SWZ128(oa));
                #pragma unroll
                for (int nt = 0; nt < 4; nt++)
                    mma_fp16(acc[mt][nt], af, &bf[nt >> 1][(nt & 1) * 2]);
            }
        }
        __syncthreads();
    }

    // ---- epilogue: per-thread row stats over its 8 cols ----
    const int g  = lane >> 2;
    const int qc = lane & 3;
    float* smax = (float*)(sm + SM_SMX);
    float* ssum = (float*)(sm + SM_SSM);
    int*   sarg = (int*)(sm + SM_SAR);

    #pragma unroll
    for (int mt = 0; mt < 4; mt++) {
        #pragma unroll
        for (int rp = 0; rp < 2; rp++) {
            const int lrow = wr * 64 + mt * 16 + rp * 8 + g;
            const int grow = rb * 128 + lrow;

            float m = -FLT_MAX;
            int ai = 0;
            #pragma unroll
            for (int nt = 0; nt < 4; nt++) {
                #pragma unroll
                for (int cp = 0; cp < 2; cp++) {
                    float x = acc[mt][nt][rp * 2 + cp];
                    int col = cb * 128 + wc * 32 + nt * 8 + qc * 2 + cp;
                    if (col == grow) g_diag[grow] = x;
                    if (x > m) { m = x; ai = col; }
                }
            }
            float s = 0.f;
            #pragma unroll
            for (int nt = 0; nt < 4; nt++)
                #pragma unroll
                for (int cp = 0; cp < 2; cp++)
                    s += __expf(acc[mt][nt][rp * 2 + cp] - m);

            #pragma unroll
            for (int off = 1; off < 4; off <<= 1) {
                float m2 = __shfl_xor_sync(0xffffffffu, m, off);
                float s2 = __shfl_xor_sync(0xffffffffu, s, off);
                int   a2 = __shfl_xor_sync(0xffffffffu, ai, off);
                if (m2 > m || (m2 == m && a2 < ai)) ai = a2;
                float NM = fmaxf(m, m2);
                s = s * __expf(m - NM) + s2 * __expf(m2 - NM);
                m = NM;
            }
            if (qc == 0) {
                smax[wc * 128 + lrow] = m;
                ssum[wc * 128 + lrow] = s;
                sarg[wc * 128 + lrow] = ai;
            }
        }
    }
    __syncthreads();

    // ---- merge 4 warp-cols; coalesced transposed write [cb][row] ----
    if (lane < 16) {
        const int lrow = wid * 16 + lane;
        const int grow = rb * 128 + lrow;
        float M = -FLT_MAX, S = 0.f;
        int AI = 0;
        #pragma unroll
        for (int w = 0; w < 4; w++) {
            float v = smax[w * 128 + lrow];
            float s = ssum[w * 128 + lrow];
            if (v > M) AI = sarg[w * 128 + lrow];   // ascending w: first-idx ties
            float NM = fmaxf(M, v);
            S = S * __expf(M - NM) + s * __expf(v - NM);
            M = NM;
        }
        int pi = cb * M_TOT + grow;
        g_pmax[pi] = M;
        g_psum[pi] = S;
        g_pami[pi] = AI;
    }
}

// ---------------------------------------------------------------------------
// Kernel 2: finalize. 1 row/thread (coalesced), block-reduce, last block
// sums the 16 partials in fixed order and writes (loss, acc).
// ---------------------------------------------------------------------------
__global__ void __launch_bounds__(256) finalize_kernel(float* __restrict__ out) {
    __shared__ float s_loss[256];
    __shared__ int   s_corr[256];
    __shared__ int   s_last;
    const int tid = threadIdx.x;
    const int r = blockIdx.x * 256 + tid;

    float Mx = -FLT_MAX;
    #pragma unroll
    for (int t = 0; t < NPART; t++) Mx = fmaxf(Mx, g_pmax[t * M_TOT + r]);

    float S = 0.f, bv = -FLT_MAX;
    int AI = 0;
    #pragma unroll
    for (int t = 0; t < NPART; t++) {
        float v = g_pmax[t * M_TOT + r];
        S += g_psum[t * M_TOT + r] * __expf(v - Mx);
        if (v > bv) { bv = v; AI = g_pami[t * M_TOT + r]; }  // first-idx ties
    }
    float lse = Mx + logf(S);

    s_loss[tid] = lse - g_diag[r];
    s_corr[tid] = (AI == r) ? 1 : 0;
    __syncthreads();
    for (int o = 128; o > 0; o >>= 1) {
        if (tid < o) {
            s_loss[tid] += s_loss[tid + o];
            s_corr[tid] += s_corr[tid + o];
        }
        __syncthreads();
    }
    if (tid == 0) {
        g_blk_loss[blockIdx.x] = s_loss[0];
        g_blk_corr[blockIdx.x] = s_corr[0];
        __threadfence();
        unsigned prev = atomicAdd(&g_done, 1u);
        s_last = (prev == NFBLK - 1) ? 1 : 0;
    }
    __syncthreads();

    if (s_last && tid == 0) {
        __threadfence();                 // see all blocks' partials
        float L = 0.f;
        int Cc = 0;
        #pragma unroll
        for (int i = 0; i < NFBLK; i++) {   // fixed order -> deterministic
            L += g_blk_loss[i];
            Cc += g_blk_corr[i];
        }
        out[0] = L / (float)M_TOT;
        out[1] = 100.f * (float)Cc / (float)M_TOT;
        g_done = 0;                      // reset for graph replay
    }
}

// ---------------------------------------------------------------------------
extern "C" void kernel_launch(void* const* d_in, const int* in_sizes, int n_in,
                              void* d_out, int out_size) {
    const float* pred = (const float*)d_in[0];
    const float* gt   = (const float*)d_in[1];

    cudaFuncSetAttribute(gemm_softmax_kernel,
                         cudaFuncAttributeMaxDynamicSharedMemorySize, SM_TOTAL);

    pack_kernel<<<2 * NPAGE, 256>>>(pred, gt);
    gemm_softmax_kernel<<<1024, 256, SM_TOTAL>>>();
    finalize_kernel<<<NFBLK, 256>>>((float*)d_out);
}